// round 3
// baseline (speedup 1.0000x reference)
#include <cuda_runtime.h>
#include <cuda_bf16.h>

// x: [20000, 512] f32 ; weight: [50] f32 ; idx: [50,2000] int32
// out[c*R + r] = x[idx[r], c] * w[r/2000],  R = 100000, C = 512
#define N_FEATURE 20000
#define N_CELL    512
#define N_CT      50
#define M_PER_CT  2000
#define R_TOTAL   (N_CT * M_PER_CT)     // 100000

#define TILE_R 32
#define TILE_C 128

// Block = 256 threads. Tile: 32 r x 128 c.
// SMEM layout: [c][r] (c-major), 128 rows x 32 floats = 16KB.
// Each 32-float smem row is 8 granules of 4 consecutive r; granule (c,r4) is
// stored at physical slot p = (r4 + 2*(c>>2)) & 7.  This makes:
//   - load-phase scalar STS conflict-free (32 distinct banks/warp, verified)
//   - store-phase LDS.128 conflict-free (8 distinct granules per quarter-warp)
__global__ __launch_bounds__(256, 8)
void celltype_scale_transpose_v2(const float4* __restrict__ x4,
                                 const float*  __restrict__ w,
                                 const int*    __restrict__ idx,
                                 float*        __restrict__ out)
{
    __shared__ float tile[TILE_C * TILE_R];   // 16 KB

    const int r0  = blockIdx.x * TILE_R;      // 3125 tiles
    const int c0  = blockIdx.y * TILE_C;      // 4 tiles
    const int tid = threadIdx.x;

    const int c4      = tid >> 3;             // 0..31  (column granule in tile)
    const int rl_base = tid & 7;

    // ---- Load phase: LDG.128 (4 consecutive c) -> 4 swizzled scalar STS ----
    #pragma unroll
    for (int i = 0; i < 4; i++) {
        const int rl = rl_base + 8 * i;       // 0..31 row in tile
        const int r  = r0 + rl;
        const int srow = idx[r];
        const float wv = w[r / M_PER_CT];

        const float4 v = x4[(size_t)srow * (N_CELL / 4) + (c0 >> 2) + c4];

        const int r4  = rl >> 2;              // 0..7 granule along r
        const int off = rl & 3;
        const int p   = (r4 + 2 * c4) & 7;    // swizzled granule slot
        const float vv[4] = {v.x, v.y, v.z, v.w};
        #pragma unroll
        for (int k = 0; k < 4; k++) {
            const int crow = 4 * c4 + k;      // smem c-row; crow>>2 == c4
            tile[crow * TILE_R + 4 * p + off] = vv[k] * wv;
        }
    }

    __syncthreads();

    // ---- Store phase: LDS.128 (4 consecutive r) -> STG.128 streaming ----
    #pragma unroll
    for (int i = 0; i < 4; i++) {
        const int c_local = (tid >> 3) + 32 * i;           // 0..127
        const int r4      = tid & 7;                       // 0..7
        const int p       = (r4 + 2 * (c_local >> 2)) & 7;
        const float4 v = *(const float4*)&tile[c_local * TILE_R + 4 * p];
        float4* dst = (float4*)&out[(size_t)(c0 + c_local) * R_TOTAL + r0 + 4 * r4];
        __stcs(dst, v);   // streaming: don't let 205MB of output evict x from L2
    }
}

extern "C" void kernel_launch(void* const* d_in, const int* in_sizes, int n_in,
                              void* d_out, int out_size)
{
    const float* x   = nullptr;
    const float* w   = nullptr;
    const int*   idx = nullptr;
    for (int i = 0; i < n_in; i++) {
        if (in_sizes[i] == N_FEATURE * N_CELL)      x   = (const float*)d_in[i];
        else if (in_sizes[i] == N_CT)               w   = (const float*)d_in[i];
        else if (in_sizes[i] == R_TOTAL)            idx = (const int*)d_in[i];
    }
    float* out = (float*)d_out;

    dim3 grid(R_TOTAL / TILE_R, N_CELL / TILE_C);   // (3125, 4)
    celltype_scale_transpose_v2<<<grid, 256>>>((const float4*)x, w, idx, out);
}

// round 4
// speedup vs baseline: 1.6762x; 1.6762x over previous
#include <cuda_runtime.h>
#include <cuda_bf16.h>

// x: [20000, 512] f32 ; weight: [50] f32 ; idx: [50,2000] int32
// out[c*R + r] = x[idx[r], c] * w[r/2000],  R = 100000, C = 512
#define N_FEATURE 20000
#define N_CELL    512
#define N_CT      50
#define M_PER_CT  2000
#define R_TOTAL   (N_CT * M_PER_CT)     // 100000

#define TILE_R 32
#define TILE_C 128

// Block = 256 threads = 8 warps. Tile: 32 r x 128 c.
// Load:  warp w owns rows r0+4w..r0+4w+3. Each row read as one dense
//        512B LDG.128 across the warp (lane = 16B granule). The thread's
//        4x4 (r x c) register block is transposed for free, then written as
//        4 STS.128 granules (4 consecutive r) into a [c][r-granule] smem
//        layout with swizzle p = (r4 + c4) & 7  -> conflict-free.
// Store: thread reads granule (c_local, r4) via LDS.128 (conflict-free),
//        writes STG.128 streaming; each 8-lane octet covers 128B contiguous.
// All four phases are 128-bit AND fully dense: 0.125 wavefronts/element,
// the L1 data-path floor for a 4-touch transpose.
__global__ __launch_bounds__(256, 8)
void celltype_scale_transpose_v3(const float4* __restrict__ x4,
                                 const float*  __restrict__ w,
                                 const int*    __restrict__ idx,
                                 float*        __restrict__ out)
{
    __shared__ float tile[TILE_C * TILE_R];   // 16 KB

    const int r0  = blockIdx.x * TILE_R;      // 3125 tiles
    const int c0  = blockIdx.y * TILE_C;      // 4 tiles
    const int tid = threadIdx.x;
    const int wp  = tid >> 5;                 // warp 0..7
    const int l   = tid & 31;                 // lane

    // ---- Load phase ----
    const int rbase = r0 + 4 * wp;
    // 4-aligned row group never crosses a celltype boundary (2000 % 4 == 0):
    const float wv = w[rbase / M_PER_CT];
    const int4 si = *(const int4*)&idx[rbase];          // warp-broadcast
    const int srow[4] = { si.x, si.y, si.z, si.w };

    float a[4][4];                                      // [row][col]
    #pragma unroll
    for (int j = 0; j < 4; j++) {
        const float4 v = x4[(size_t)srow[j] * (N_CELL / 4) + (c0 >> 2) + l];
        a[j][0] = v.x * wv; a[j][1] = v.y * wv;
        a[j][2] = v.z * wv; a[j][3] = v.w * wv;
    }

    const int p = (wp + l) & 7;                          // granule swizzle
    #pragma unroll
    for (int k = 0; k < 4; k++) {
        const int crow = 4 * l + k;                      // c within tile
        const float4 g = make_float4(a[0][k], a[1][k], a[2][k], a[3][k]);
        *(float4*)&tile[crow * TILE_R + 4 * p] = g;      // STS.128
    }

    __syncthreads();

    // ---- Store phase ----
    #pragma unroll
    for (int i = 0; i < 4; i++) {
        const int c_local = (tid >> 3) + 32 * i;         // 0..127
        const int r4      = tid & 7;                     // 0..7
        const int pp      = (r4 + (c_local >> 2)) & 7;
        const float4 v = *(const float4*)&tile[c_local * TILE_R + 4 * pp];
        float4* dst = (float4*)&out[(size_t)(c0 + c_local) * R_TOTAL + r0 + 4 * r4];
        __stcs(dst, v);   // streaming: keep x resident in L2
    }
}

extern "C" void kernel_launch(void* const* d_in, const int* in_sizes, int n_in,
                              void* d_out, int out_size)
{
    const float* x   = nullptr;
    const float* w   = nullptr;
    const int*   idx = nullptr;
    for (int i = 0; i < n_in; i++) {
        if (in_sizes[i] == N_FEATURE * N_CELL)      x   = (const float*)d_in[i];
        else if (in_sizes[i] == N_CT)               w   = (const float*)d_in[i];
        else if (in_sizes[i] == R_TOTAL)            idx = (const int*)d_in[i];
    }
    float* out = (float*)d_out;

    dim3 grid(R_TOTAL / TILE_R, N_CELL / TILE_C);   // (3125, 4)
    celltype_scale_transpose_v3<<<grid, 256>>>((const float4*)x, w, idx, out);
}

// round 5
// speedup vs baseline: 1.6965x; 1.0121x over previous
#include <cuda_runtime.h>
#include <cuda_bf16.h>

// x: [20000, 512] f32 ; weight: [50] f32 ; idx: [50,2000] int32
// out[c*R + r] = x[idx[r], c] * w[r/2000],  R = 100000, C = 512
#define N_FEATURE 20000
#define N_CELL    512
#define N_CT      50
#define M_PER_CT  2000
#define R_TOTAL   (N_CT * M_PER_CT)     // 100000

#define TILE_R 32
#define TILE_C 128
#define NITER  5                        // r-tiles per block; 3125 = 5 * 625

// SMEM tile layout: row-major [row][granule], granule = 16B (4 consecutive c).
// Granule (row, c4) stored at slot s = c4 ^ ((row>>2) & 7).
//  - cp.async writes: row fixed per warp-iteration -> 32 distinct slots, dense.
//  - store-phase scalar LDS (element (4*r4+k, c)): banks all distinct per warp.
__device__ __forceinline__ void issue_tile(const float4* __restrict__ x4,
                                           const int* __restrict__ idx,
                                           float* __restrict__ buf,
                                           int r0, int c0, int wp, int l)
{
    #pragma unroll
    for (int i = 0; i < 4; i++) {
        const int row  = 8 * i + wp;                 // 0..31
        const int srow = __ldg(&idx[r0 + row]);      // warp-uniform broadcast
        const int s    = l ^ ((row >> 2) & 7);       // swizzled granule slot
        const float4* src = &x4[(size_t)srow * (N_CELL / 4) + (c0 >> 2) + l];
        unsigned dst = (unsigned)__cvta_generic_to_shared(&buf[row * TILE_C + 4 * s]);
        asm volatile("cp.async.cg.shared.global [%0], [%1], 16;\n"
                     :: "r"(dst), "l"(src));
    }
    asm volatile("cp.async.commit_group;\n");
}

__global__ __launch_bounds__(256)
void celltype_scale_transpose_v4(const float4* __restrict__ x4,
                                 const float*  __restrict__ w,
                                 const int*    __restrict__ idx,
                                 float*        __restrict__ out)
{
    __shared__ float buf[2][TILE_R * TILE_C];        // 2 x 16 KB

    const int rbase = blockIdx.x * (TILE_R * NITER); // 625 groups of 160 rows
    const int c0    = blockIdx.y * TILE_C;           // 4 c-tiles
    const int tid   = threadIdx.x;
    const int wp    = tid >> 5;
    const int l     = tid & 31;

    issue_tile(x4, idx, buf[0], rbase, c0, wp, l);

    #pragma unroll
    for (int t = 0; t < NITER; t++) {
        const int r0 = rbase + t * TILE_R;

        if (t + 1 < NITER) {
            issue_tile(x4, idx, buf[(t + 1) & 1], r0 + TILE_R, c0, wp, l);
            asm volatile("cp.async.wait_group 1;\n");
        } else {
            asm volatile("cp.async.wait_group 0;\n");
        }
        __syncthreads();

        // ---- scale + transpose-store from buf[t&1] ----
        const float* b  = buf[t & 1];
        const int    r4 = tid & 7;                   // r-granule 0..7
        const float  wv = w[(r0 + 4 * r4) / M_PER_CT];  // 4-aligned, one celltype

        #pragma unroll
        for (int i = 0; i < 4; i++) {
            const int c   = (tid >> 3) + 32 * i;     // 0..127
            const int c4g = c >> 2;
            const int dd  = c & 3;
            const int s   = c4g ^ r4;                // (row>>2)&7 == r4 for k<4
            float v[4];
            #pragma unroll
            for (int k = 0; k < 4; k++) {
                const int row = 4 * r4 + k;
                v[k] = b[row * TILE_C + 4 * s + dd] * wv;
            }
            float4* dst = (float4*)&out[(size_t)(c0 + c) * R_TOTAL + r0 + 4 * r4];
            __stcs(dst, make_float4(v[0], v[1], v[2], v[3]));
        }
        __syncthreads();   // buffer (t&1) is reused by iteration t+1's prefetch of t+2
    }
}

extern "C" void kernel_launch(void* const* d_in, const int* in_sizes, int n_in,
                              void* d_out, int out_size)
{
    const float* x   = nullptr;
    const float* w   = nullptr;
    const int*   idx = nullptr;
    for (int i = 0; i < n_in; i++) {
        if (in_sizes[i] == N_FEATURE * N_CELL)      x   = (const float*)d_in[i];
        else if (in_sizes[i] == N_CT)               w   = (const float*)d_in[i];
        else if (in_sizes[i] == R_TOTAL)            idx = (const int*)d_in[i];
    }
    float* out = (float*)d_out;

    dim3 grid(R_TOTAL / (TILE_R * NITER), N_CELL / TILE_C);   // (625, 4)
    celltype_scale_transpose_v4<<<grid, 256>>>((const float4*)x, w, idx, out);
}

// round 6
// speedup vs baseline: 1.6977x; 1.0007x over previous
#include <cuda_runtime.h>
#include <cuda_bf16.h>

// x: [20000, 512] f32 ; weight: [50] f32 ; idx: [50,2000] int32
// out[c*R + r] = x[idx[r], c] * w[r/2000],  R = 100000, C = 512
#define N_FEATURE 20000
#define N_CELL    512
#define N_CT      50
#define M_PER_CT  2000
#define R_TOTAL   (N_CT * M_PER_CT)     // 100000

#define TILE_R 32
#define TILE_C 128
#define NITER  5                        // r-tiles per block; 3125 = 5 * 625

// SMEM tile: row-major [row][granule16B], granule (row,c4) at slot
// s = c4 ^ ((row>>2)&7).  cp.async writes dense 512B/row; store-phase
// scalar LDS conflict-free (all 32 banks distinct per warp).
__device__ __forceinline__ void issue_tile(const float4* __restrict__ x4,
                                           const int* __restrict__ idx,
                                           float* __restrict__ buf,
                                           int r0, int c0q, int wp, int l)
{
    #pragma unroll
    for (int i = 0; i < 4; i++) {
        const int row  = 8 * i + wp;                 // 0..31
        const int srow = __ldg(&idx[r0 + row]);      // warp-uniform broadcast
        const int s    = l ^ ((row >> 2) & 7);       // swizzled granule slot
        const float4* src = &x4[(size_t)srow * (N_CELL / 4) + c0q + l];
        unsigned dst = (unsigned)__cvta_generic_to_shared(&buf[row * TILE_C + 4 * s]);
        asm volatile("cp.async.cg.shared.global [%0], [%1], 16;\n"
                     :: "r"(dst), "l"(src));
    }
    asm volatile("cp.async.commit_group;\n");
}

__global__ __launch_bounds__(256, 7)
void celltype_scale_transpose_v5(const float4* __restrict__ x4,
                                 const float*  __restrict__ w,
                                 const int*    __restrict__ idx,
                                 float*        __restrict__ out)
{
    __shared__ float buf[2][TILE_R * TILE_C];        // exactly 32 KB

    const int rbase = blockIdx.x * (TILE_R * NITER); // 625 groups of 160 rows
    const int c0    = blockIdx.y * TILE_C;           // 4 c-tiles
    const int c0q   = c0 >> 2;
    const int tid   = threadIdx.x;
    const int wp    = tid >> 5;
    const int l     = tid & 31;

    // Store-phase invariants (constant across iterations):
    const int r4   = tid & 7;                        // r-granule 0..7
    const int chi  = tid >> 3;                       // c base 0..31
    const int c4g0 = chi >> 2;
    const int dd   = chi & 3;                        // c&3 is iter-invariant (+32 steps)

    issue_tile(x4, idx, buf[0], rbase, c0q, wp, l);

    #pragma unroll
    for (int t = 0; t < NITER; t++) {
        const int r0 = rbase + t * TILE_R;

        if (t + 1 < NITER) {
            issue_tile(x4, idx, buf[(t + 1) & 1], r0 + TILE_R, c0q, wp, l);
            asm volatile("cp.async.wait_group 1;\n");
        } else {
            asm volatile("cp.async.wait_group 0;\n");
        }
        __syncthreads();

        // ---- scale + transpose-store from buf[t&1] ----
        const float* b  = buf[t & 1] + 4 * r4 * TILE_C + dd;  // rows 4r4..4r4+3
        const float wv  = w[(unsigned)(r0 + 4 * r4) / M_PER_CT]; // 4-aligned group
        float* outb = out + (size_t)(c0 + chi) * R_TOTAL + r0 + 4 * r4;

        #pragma unroll
        for (int i = 0; i < 4; i++) {
            const int s = ((c4g0 + 8 * i) ^ r4) * 4;  // swizzled granule offset
            float4 v;
            v.x = b[0 * TILE_C + s] * wv;
            v.y = b[1 * TILE_C + s] * wv;
            v.z = b[2 * TILE_C + s] * wv;
            v.w = b[3 * TILE_C + s] * wv;
            __stcs((float4*)(outb + (size_t)(32 * i) * R_TOTAL), v);
        }
        __syncthreads();   // buf[t&1] reused by next iteration's prefetch
    }
}

extern "C" void kernel_launch(void* const* d_in, const int* in_sizes, int n_in,
                              void* d_out, int out_size)
{
    const float* x   = nullptr;
    const float* w   = nullptr;
    const int*   idx = nullptr;
    for (int i = 0; i < n_in; i++) {
        if (in_sizes[i] == N_FEATURE * N_CELL)      x   = (const float*)d_in[i];
        else if (in_sizes[i] == N_CT)               w   = (const float*)d_in[i];
        else if (in_sizes[i] == R_TOTAL)            idx = (const int*)d_in[i];
    }
    float* out = (float*)d_out;

    dim3 grid(R_TOTAL / (TILE_R * NITER), N_CELL / TILE_C);   // (625, 4)
    celltype_scale_transpose_v5<<<grid, 256>>>((const float4*)x, w, idx, out);
}

// round 7
// speedup vs baseline: 1.7485x; 1.0300x over previous
#include <cuda_runtime.h>
#include <cuda_bf16.h>

// x: [20000, 512] f32 ; weight: [50] f32 ; idx: [50,2000] int32
// out[c*R + r] = x[idx[r], c] * w[r/2000],  R = 100000, C = 512
#define N_FEATURE 20000
#define N_CELL    512
#define N_CT      50
#define M_PER_CT  2000
#define R_TOTAL   (N_CT * M_PER_CT)     // 100000

#define TILE_R 32
#define TILE_C 64
#define NITER  5                        // r-tiles per block; 3125 = 5 * 625

// SMEM tile: row-major [row][granule16B], 16 granules/row.
// Granule (row, g) stored at slot s = g ^ ((row>>2) & 7).
//  - cp.async: half-warp per row -> 16 distinct slots, 256B dense gmem read.
//  - store-phase scalar LDS: per warp c4 fixed, banks 4*(c4^r4)+dd all
//    distinct over r4 in 0..7, dd in 0..3 -> conflict-free.
//  - STG.128: each 8-lane octet writes 128B contiguous (32 consecutive r).
__device__ __forceinline__ void issue_tile(const float4* __restrict__ x4,
                                           const int* __restrict__ idx,
                                           float* __restrict__ buf,
                                           int r0, int c0q, int hw, int g)
{
    #pragma unroll
    for (int i = 0; i < 2; i++) {
        const int row  = 16 * i + hw;                // 0..31, half-warp uniform
        const int srow = __ldg(&idx[r0 + row]);      // broadcast
        const int s    = g ^ ((row >> 2) & 7);       // swizzled granule slot
        const float4* src = &x4[(size_t)srow * (N_CELL / 4) + c0q + g];
        unsigned dst = (unsigned)__cvta_generic_to_shared(&buf[row * TILE_C + 4 * s]);
        asm volatile("cp.async.cg.shared.global [%0], [%1], 16;\n"
                     :: "r"(dst), "l"(src));
    }
    asm volatile("cp.async.commit_group;\n");
}

__global__ __launch_bounds__(256, 8)
void celltype_scale_transpose_v6(const float4* __restrict__ x4,
                                 const float*  __restrict__ w,
                                 const int*    __restrict__ idx,
                                 float*        __restrict__ out)
{
    __shared__ float buf[2][TILE_R * TILE_C];        // 2 x 8 KB = 16 KB

    const int rbase = blockIdx.x * (TILE_R * NITER); // 625 groups of 160 rows
    const int c0    = blockIdx.y * TILE_C;           // 8 c-tiles
    const int c0q   = c0 >> 2;
    const int tid   = threadIdx.x;
    const int hw    = tid >> 4;                      // half-warp id 0..15
    const int g     = tid & 15;                      // granule 0..15

    // Store-phase invariants:
    const int r4   = tid & 7;                        // r-granule 0..7
    const int chi  = tid >> 3;                       // c base 0..31
    const int c4g0 = chi >> 2;
    const int dd   = chi & 3;

    issue_tile(x4, idx, buf[0], rbase, c0q, hw, g);

    #pragma unroll
    for (int t = 0; t < NITER; t++) {
        const int r0 = rbase + t * TILE_R;

        if (t + 1 < NITER) {
            issue_tile(x4, idx, buf[(t + 1) & 1], r0 + TILE_R, c0q, hw, g);
            asm volatile("cp.async.wait_group 1;\n");
        } else {
            asm volatile("cp.async.wait_group 0;\n");
        }
        __syncthreads();

        // ---- scale + transpose-store from buf[t&1] ----
        const float* b  = buf[t & 1] + 4 * r4 * TILE_C + dd;     // rows 4r4..+3
        const float wv  = w[(unsigned)(r0 + 4 * r4) / M_PER_CT]; // 4-aligned
        float* outb = out + (size_t)(c0 + chi) * R_TOTAL + r0 + 4 * r4;

        #pragma unroll
        for (int i = 0; i < 2; i++) {
            const int s = ((c4g0 + 8 * i) ^ r4) * 4;  // swizzled granule offset
            float4 v;
            v.x = b[0 * TILE_C + s] * wv;
            v.y = b[1 * TILE_C + s] * wv;
            v.z = b[2 * TILE_C + s] * wv;
            v.w = b[3 * TILE_C + s] * wv;
            __stcs((float4*)(outb + (size_t)(32 * i) * R_TOTAL), v);
        }
        __syncthreads();   // buf[t&1] reused by next iteration's prefetch
    }
}

extern "C" void kernel_launch(void* const* d_in, const int* in_sizes, int n_in,
                              void* d_out, int out_size)
{
    const float* x   = nullptr;
    const float* w   = nullptr;
    const int*   idx = nullptr;
    for (int i = 0; i < n_in; i++) {
        if (in_sizes[i] == N_FEATURE * N_CELL)      x   = (const float*)d_in[i];
        else if (in_sizes[i] == N_CT)               w   = (const float*)d_in[i];
        else if (in_sizes[i] == R_TOTAL)            idx = (const int*)d_in[i];
    }
    float* out = (float*)d_out;

    dim3 grid(R_TOTAL / (TILE_R * NITER), N_CELL / TILE_C);   // (625, 8)
    celltype_scale_transpose_v6<<<grid, 256>>>((const float4*)x, w, idx, out);
}

// round 8
// speedup vs baseline: 1.7498x; 1.0007x over previous
#include <cuda_runtime.h>
#include <cuda_bf16.h>

// x: [20000, 512] f32 ; weight: [50] f32 ; idx: [50,2000] int32
// out[c*R + r] = x[idx[r], c] * w[r/2000],  R = 100000, C = 512
#define N_FEATURE 20000
#define N_CELL    512
#define N_CT      50
#define M_PER_CT  2000
#define R_TOTAL   (N_CT * M_PER_CT)     // 100000

#define TILE_R 32
#define TILE_C 64
#define NITER  5                        // r-tiles per block; 3125 = 5 * 625
#define STAGES 3                        // ring buffer depth

// SMEM tile: row-major [row][granule16B], 16 granules/row.
// Granule (row, g) at slot s = g ^ ((row>>2) & 7).
//  - cp.async: half-warp per row -> 16 distinct slots, 256B dense gmem read.
//  - store-phase scalar LDS: banks 4*(c4^r4)+dd all distinct per warp.
//  - STG.128: each 8-lane octet writes 128B contiguous.
__device__ __forceinline__ void issue_tile(const float4* __restrict__ x4,
                                           const int* __restrict__ idx,
                                           float* __restrict__ buf,
                                           int r0, int c0q, int hw, int g)
{
    #pragma unroll
    for (int i = 0; i < 2; i++) {
        const int row  = 16 * i + hw;                // 0..31, half-warp uniform
        const int srow = __ldg(&idx[r0 + row]);      // broadcast
        const int s    = g ^ ((row >> 2) & 7);       // swizzled granule slot
        const float4* src = &x4[(size_t)srow * (N_CELL / 4) + c0q + g];
        unsigned dst = (unsigned)__cvta_generic_to_shared(&buf[row * TILE_C + 4 * s]);
        asm volatile("cp.async.cg.shared.global [%0], [%1], 16;\n"
                     :: "r"(dst), "l"(src));
    }
    asm volatile("cp.async.commit_group;\n");
}

__global__ __launch_bounds__(256, 8)
void celltype_scale_transpose_v7(const float4* __restrict__ x4,
                                 const float*  __restrict__ w,
                                 const int*    __restrict__ idx,
                                 float*        __restrict__ out)
{
    __shared__ float buf[STAGES][TILE_R * TILE_C];   // 3 x 8 KB = 24 KB

    const int rbase = blockIdx.x * (TILE_R * NITER); // 625 groups of 160 rows
    const int c0    = blockIdx.y * TILE_C;           // 8 c-tiles
    const int c0q   = c0 >> 2;
    const int tid   = threadIdx.x;
    const int hw    = tid >> 4;                      // half-warp id 0..15
    const int g     = tid & 15;                      // granule 0..15

    // Store-phase invariants:
    const int r4   = tid & 7;                        // r-granule 0..7
    const int chi  = tid >> 3;                       // c base 0..31
    const int c4g0 = chi >> 2;
    const int dd   = chi & 3;

    // Prologue: two tiles in flight.
    issue_tile(x4, idx, buf[0], rbase,          c0q, hw, g);
    issue_tile(x4, idx, buf[1], rbase + TILE_R, c0q, hw, g);

    #pragma unroll
    for (int t = 0; t < NITER; t++) {
        const int r0 = rbase + t * TILE_R;

        // Wait for tile t's group. Pending at this point: {t, t+1} (or {t} at end).
        if (t + 1 < NITER) asm volatile("cp.async.wait_group 1;\n");
        else               asm volatile("cp.async.wait_group 0;\n");
        // Single barrier: makes tile t visible to all threads AND guarantees
        // everyone finished reading tile t-1 (the buffer tile t+2 overwrites).
        __syncthreads();

        // Kick off tile t+2 before consuming t: overlaps its gathered reads
        // with this iteration's store stream.
        if (t + 2 < NITER)
            issue_tile(x4, idx, buf[(t + 2) % STAGES], r0 + 2 * TILE_R, c0q, hw, g);

        // ---- scale + transpose-store from buf[t % STAGES] ----
        const float* b  = buf[t % STAGES] + 4 * r4 * TILE_C + dd;  // rows 4r4..+3
        const float wv  = w[(unsigned)(r0 + 4 * r4) / M_PER_CT];   // 4-aligned
        float* outb = out + (size_t)(c0 + chi) * R_TOTAL + r0 + 4 * r4;

        #pragma unroll
        for (int i = 0; i < 2; i++) {
            const int s = ((c4g0 + 8 * i) ^ r4) * 4;  // swizzled granule offset
            float4 v;
            v.x = b[0 * TILE_C + s] * wv;
            v.y = b[1 * TILE_C + s] * wv;
            v.z = b[2 * TILE_C + s] * wv;
            v.w = b[3 * TILE_C + s] * wv;
            __stcs((float4*)(outb + (size_t)(32 * i) * R_TOTAL), v);
        }
        // No second barrier: next iteration's post-wait __syncthreads covers
        // buffer-reuse safety (3-stage ring).
    }
}

extern "C" void kernel_launch(void* const* d_in, const int* in_sizes, int n_in,
                              void* d_out, int out_size)
{
    const float* x   = nullptr;
    const float* w   = nullptr;
    const int*   idx = nullptr;
    for (int i = 0; i < n_in; i++) {
        if (in_sizes[i] == N_FEATURE * N_CELL)      x   = (const float*)d_in[i];
        else if (in_sizes[i] == N_CT)               w   = (const float*)d_in[i];
        else if (in_sizes[i] == R_TOTAL)            idx = (const int*)d_in[i];
    }
    float* out = (float*)d_out;

    dim3 grid(R_TOTAL / (TILE_R * NITER), N_CELL / TILE_C);   // (625, 8)
    celltype_scale_transpose_v7<<<grid, 256>>>((const float4*)x, w, idx, out);
}